// round 12
// baseline (speedup 1.0000x reference)
#include <cuda_runtime.h>
#include <math.h>

#define B_SZ 32
#define T_SZ 1024
#define I_SZ 512
#define H_SZ 1024
#define DT_C 0.1f

typedef unsigned long long ull;

// ---------------- f32x2 packed-math helpers (Blackwell FFMA2) -------------
__device__ __forceinline__ ull ffma2(ull a, ull b, ull c) {
    ull d; asm("fma.rn.f32x2 %0, %1, %2, %3;" : "=l"(d) : "l"(a), "l"(b), "l"(c)); return d;
}
__device__ __forceinline__ ull fadd2(ull a, ull b) {
    ull d; asm("add.rn.f32x2 %0, %1, %2;" : "=l"(d) : "l"(a), "l"(b)); return d;
}
__device__ __forceinline__ ull pack2(float lo, float hi) {
    ull d; asm("mov.b64 %0, {%1, %2};" : "=l"(d) : "f"(lo), "f"(hi)); return d;
}
__device__ __forceinline__ float2 unpack2(ull v) {
    float2 r; asm("mov.b64 {%0, %1}, %2;" : "=f"(r.x), "=f"(r.y) : "l"(v)); return r;
}
// Acquire load for producer-flag polls (orders subsequent loads after flag).
__device__ __forceinline__ int ld_acq(const volatile int* p) {
    int v;
    asm volatile("ld.acquire.gpu.global.s32 %0, [%1];"
                 : "=r"(v) : "l"((const int*)p) : "memory");
    return v;
}

// ------------------------------------------------------------------
// Persistent-kernel global state
// g_hT: transposed hidden state double buffer: [2][H][B]  (k-major)
// g_arrive[blk]: h for step t+1 published (set end of step t)
// g_staged[blk]: staging of step s complete -> value s+1
// All flags line-padded, monotonic, single-writer.
// ------------------------------------------------------------------
#define RBLK 128
#define FPAD 32                      // ints per flag slot (128B line)
__device__ float g_hT[2][H_SZ * B_SZ];
__device__ volatile int g_arrive[RBLK * FPAD];
__device__ volatile int g_staged[RBLK * FPAD];

__global__ void reset_kernel() {
    int idx = blockIdx.x * blockDim.x + threadIdx.x;
    if (idx < H_SZ * B_SZ) g_hT[0][idx] = 0.0f;
    if (idx < RBLK * FPAD) { g_arrive[idx] = 0; g_staged[idx] = 0; }
}

// ------------------------------------------------------------------
// xW GEMM: C[M=B*T, H] = X[M, I] @ W[H, I]^T   (fp32, FFMA2 inner)
// 128x64 block tile, BK=16, 256 threads  (R8/R11-proven)
// ------------------------------------------------------------------
#define GBM 128
#define GBN 64
#define GBK 16

union F4U { float4 f4; ull u[2]; };

__global__ void __launch_bounds__(256) gemm_xw(
    const float* __restrict__ X, const float* __restrict__ W,
    float* __restrict__ C)
{
    __shared__ float Xs[GBK][GBM];
    __shared__ float Ws[GBK][GBN + 4];
    const int tid = threadIdx.x;
    const int tx = tid & 15;   // 16 -> N
    const int ty = tid >> 4;   // 16 -> M
    const int m0 = blockIdx.y * GBM;
    const int n0 = blockIdx.x * GBN;

    ull acc2[4][4];   // [m-pair p][n j]
#pragma unroll
    for (int p = 0; p < 4; p++)
#pragma unroll
        for (int j = 0; j < 4; j++) acc2[p][j] = 0ull;

    for (int k0 = 0; k0 < I_SZ; k0 += GBK) {
#pragma unroll
        for (int pp = 0; pp < 2; pp++) {
            int q = tid + pp * 256;
            int row = q >> 2, qc = q & 3;
            float4 v = *(const float4*)(X + (size_t)(m0 + row) * I_SZ + k0 + qc * 4);
            Xs[qc * 4 + 0][row] = v.x; Xs[qc * 4 + 1][row] = v.y;
            Xs[qc * 4 + 2][row] = v.z; Xs[qc * 4 + 3][row] = v.w;
        }
        {
            int row = tid >> 2, qc = tid & 3;
            float4 v = *(const float4*)(W + (size_t)(n0 + row) * I_SZ + k0 + qc * 4);
            Ws[qc * 4 + 0][row] = v.x; Ws[qc * 4 + 1][row] = v.y;
            Ws[qc * 4 + 2][row] = v.z; Ws[qc * 4 + 3][row] = v.w;
        }
        __syncthreads();
#pragma unroll
        for (int kk = 0; kk < GBK; kk++) {
            F4U a0, a1;
            a0.f4 = *(const float4*)&Xs[kk][ty * 8];
            a1.f4 = *(const float4*)&Xs[kk][ty * 8 + 4];
            float4 bv = *(const float4*)&Ws[kk][tx * 4];
            ull bd[4];
            bd[0] = pack2(bv.x, bv.x); bd[1] = pack2(bv.y, bv.y);
            bd[2] = pack2(bv.z, bv.z); bd[3] = pack2(bv.w, bv.w);
            ull a2[4] = {a0.u[0], a0.u[1], a1.u[0], a1.u[1]};
#pragma unroll
            for (int p = 0; p < 4; p++)
#pragma unroll
                for (int j = 0; j < 4; j++)
                    acc2[p][j] = ffma2(a2[p], bd[j], acc2[p][j]);
        }
        __syncthreads();
    }
#pragma unroll
    for (int p = 0; p < 4; p++) {
        float2 c0 = unpack2(acc2[p][0]);
        float2 c1 = unpack2(acc2[p][1]);
        float2 c2 = unpack2(acc2[p][2]);
        float2 c3 = unpack2(acc2[p][3]);
        float4 lo = make_float4(c0.x, c1.x, c2.x, c3.x);
        float4 hi = make_float4(c0.y, c1.y, c2.y, c3.y);
        *(float4*)(C + (size_t)(m0 + ty * 8 + 2 * p)     * H_SZ + n0 + tx * 4) = lo;
        *(float4*)(C + (size_t)(m0 + ty * 8 + 2 * p + 1) * H_SZ + n0 + tx * 4) = hi;
    }
}

// ------------------------------------------------------------------
// Persistent recurrence kernel (R11 compute path; epilogue/staging overlap).
// grid = 128 blocks (64 j-tiles x 2 b-halves), 512 threads.
// Staging at loop TAIL: warps 4-15 stage step t+1 while warps 0-3 run
// the epilogue; then warps 0-3 stage their 16 chunks.
// ------------------------------------------------------------------
#define JT 16
#define BHALF 16
#define USTR 1025
#define HSTR 20
#define NPO 128
#define RECUR_SMEM ((JT * USTR + H_SZ * HSTR) * 4 + NPO * 64 * 8)

__device__ __forceinline__ void stage_chunk(float* hs, int gbase, int bg0,
                                            int ch, int lc, int t_next,
                                            int cur_next) {
    const volatile int* pf = &g_arrive[(gbase | ch) * FPAD];
    while (ld_acq(pf) < t_next) { }
    const float* gsrc = g_hT[cur_next] + bg0 + (size_t)(16 * ch) * B_SZ;
    float* hdst = hs + (16 * ch) * HSTR;
#pragma unroll
    for (int i = 0; i < 8; i++) {
        int f = lc + 8 * i;                 // 0..63 float4s in chunk
        int row = f >> 2, part = (f & 3) * 4;
        float4 v = __ldcg((const float4*)(gsrc + (size_t)row * B_SZ + part));
        float* d = hdst + row * HSTR + part;
        d[0] = v.x; d[1] = v.y; d[2] = v.z; d[3] = v.w;
    }
}

__global__ void __launch_bounds__(512, 1) recur_kernel(
    float* __restrict__ states,      // [B, T, H] (holds xW on entry, states on exit)
    float* __restrict__ hfinal,      // [B, H]
    const float* __restrict__ U,     // [H, H]
    const float* __restrict__ bias,  // [H]
    const float* __restrict__ tau)   // [H]
{
    extern __shared__ float sm[];
    float* Us = sm;                                 // [JT][USTR]
    float* hs = Us + JT * USTR;                     // [1024][HSTR]
    ull* red = (ull*)(hs + H_SZ * HSTR);            // [NPO][64]

    const int tid = threadIdx.x;
    const int blk = blockIdx.x;
    const int jt = blk & 63;
    const int bh = blk >> 6;
    const int j0 = jt * JT;
    const int bg0 = bh * BHALF;
    const int gbase = bh << 6;        // first block of this flag group

    const int tb = tid & 1;
    const int tj = (tid >> 1) & 3;
    const int ks = tid >> 3;      // 0..63

    // ---- staging chunk assignment ----
    // warps 0-3  (tid < 128): 16 chunks jt..jt+15 (incl. self; staged late)
    // warps 4-15 (tid >=128): 48 chunks jt+16..jt+63 (staged early)
    const int ch = (tid < 128) ? ((jt + (tid >> 3)) & 63)
                               : ((jt + 16 + ((tid - 128) >> 3)) & 63);
    const int lc = tid & 7;

    // ---- load U slab into smem: Us[row][k], row = 0..15 ----
    for (int q = tid; q < JT * (H_SZ / 4); q += 512) {
        int row = q >> 8;
        int c = (q & 255) * 4;
        float4 v = *(const float4*)(U + (size_t)(j0 + row) * H_SZ + c);
        float* d = Us + row * USTR + c;
        d[0] = v.x; d[1] = v.y; d[2] = v.z; d[3] = v.w;
    }

    // ---- epilogue (reader) setup: tid < 128, sr = tid & 15 ----
    int po = 0, sr = 0, jg = 0, bp = 0;
    float decay = 0.0f, biasj = 0.0f;
    size_t sidx0 = 0, sidx1 = 0;
    float xwA = 0.0f, xwB = 0.0f;
    if (tid < NPO) {
        int r = tid;
        po = ((r >> 1) & 1) | ((r & 1) << 1) | (((r >> 4) & 1) << 2)
           | (((r >> 5) & 1) << 3) | (((r >> 6) & 1) << 4)
           | (((r >> 2) & 1) << 5) | (((r >> 3) & 1) << 6);
        sr = r & 15;
        int j_loc = po >> 3;
        bp = po & 7;
        jg = j0 + j_loc;
        float it = 1.0f / tau[jg];
        decay = 1.0f - DT_C * it;
        biasj = bias[jg];
        int b_glob = bg0 + 2 * bp;
        sidx0 = (size_t)b_glob * T_SZ * H_SZ + jg;
        sidx1 = sidx0 + (size_t)T_SZ * H_SZ;
        xwA = __ldcg(states + sidx0);   // prefetch t = 0
        xwB = __ldcg(states + sidx1);
    }

    int cur = 0;

    // ---- prologue: stage step 0 (flags start at 0 -> poll passes) ----
    stage_chunk(hs, gbase, bg0, ch, lc, 0, 0);
    __syncthreads();
    if (tid == 0) {
        __threadfence();
        g_staged[blk * FPAD] = 1;       // done reading g_hT buf for step 0
    }

    for (int t = 0; t < T_SZ; t++) {
        // ---- compute: acc2[jj][m] over k = ks + 64*kq ----
        ull acc2[4][4];
#pragma unroll
        for (int jj = 0; jj < 4; jj++)
#pragma unroll
            for (int m = 0; m < 4; m++) acc2[jj][m] = 0ull;

        const float* urow = Us + tj * 4 * USTR + ks;
#pragma unroll
        for (int kq = 0; kq < 16; kq++) {
            int k = ks + 64 * kq;
            const float* hrow = hs + k * HSTR + 2 * tb;
            ull h0 = *(const ull*)(hrow + 0);
            ull h1 = *(const ull*)(hrow + 4);
            ull h2 = *(const ull*)(hrow + 8);
            ull h3 = *(const ull*)(hrow + 12);
#pragma unroll
            for (int jj = 0; jj < 4; jj++) {
                float us = urow[jj * USTR + 64 * kq];
                ull ud = pack2(us, us);
                acc2[jj][0] = ffma2(ud, h0, acc2[jj][0]);
                acc2[jj][1] = ffma2(ud, h1, acc2[jj][1]);
                acc2[jj][2] = ffma2(ud, h2, acc2[jj][2]);
                acc2[jj][3] = ffma2(ud, h3, acc2[jj][3]);
            }
        }

        // ---- write partials, XOR-swizzled (2-phase-optimal STS.64) ----
#pragma unroll
        for (int jj = 0; jj < 4; jj++)
#pragma unroll
            for (int m = 0; m < 4; m++) {
                int p = (tj * 4 + jj) * 8 + 2 * m + tb;
                int col = ks ^ ((m & 1) | (tb << 1) | (tj << 2));
                red[p * 64 + col] = acc2[jj][m];
            }
        __syncthreads();

        // ---- reduce (tid<128)  ||  write-permission poll (tid 256..319) ---
        float2 sum = make_float2(0.0f, 0.0f);
        float2 hold = make_float2(0.0f, 0.0f);
        if (tid < NPO) {
            ull s01 = 0ull, s23 = 0ull;
#pragma unroll
            for (int i = 0; i < 64; i += 2) {
                s01 = fadd2(s01, red[po * 64 + (i ^ sr)]);
                s23 = fadd2(s23, red[po * 64 + ((i + 1) ^ sr)]);
            }
            sum = unpack2(fadd2(s01, s23));
            hold = *(const float2*)(hs + jg * HSTR + 2 * bp);
        } else if (tid >= 256 && tid < 320) {
            // peers must have staged step t-1 before we overwrite the buffer
            // they read (g_hT[cur^1]); g_staged >= t encodes exactly that.
            while (g_staged[(gbase + (tid - 256)) * FPAD] < t) { }
        }
        __syncthreads();
        // hs is now dead until restaged: epilogue uses only registers.

        if (tid < NPO) {
            // ---- pointwise epilogue + h publish (warps 0-3) ----
            float a0 = tanhf(xwA + sum.x + biasj);
            float a1 = tanhf(xwB + sum.y + biasj);
            float h0n = decay * hold.x + DT_C * a0;
            float h1n = decay * hold.y + DT_C * a1;
            size_t off = (size_t)t * H_SZ;
            __stcg(states + sidx0 + off, h0n);
            __stcg(states + sidx1 + off, h1n);
            float2 hn = make_float2(h0n, h1n);
            __stcg((float2*)(g_hT[cur ^ 1] + (size_t)jg * B_SZ + bg0 + 2 * bp), hn);
            if (t == T_SZ - 1) {
                __stcg(hfinal + (size_t)(bg0 + 2 * bp) * H_SZ + jg, h0n);
                __stcg(hfinal + (size_t)(bg0 + 2 * bp + 1) * H_SZ + jg, h1n);
            } else {
                xwA = __ldcg(states + sidx0 + off + H_SZ);   // prefetch t+1
                xwB = __ldcg(states + sidx1 + off + H_SZ);
            }
            // order all 128 epilogue threads' stores before the flag
            asm volatile("bar.sync 1, 128;" ::: "memory");
            if (tid == 0) {
                __threadfence();
                g_arrive[blk * FPAD] = t + 1;
            }
        }

        // ---- stage step t+1: warps 4-15 immediately, warps 0-3 after
        //      their epilogue (their chunks' flags are mostly set by then) --
        if (t + 1 < T_SZ) {
            stage_chunk(hs, gbase, bg0, ch, lc, t + 1, cur ^ 1);
        }
        __syncthreads();
        if (tid == 0 && t + 1 < T_SZ) {
            __threadfence();
            g_staged[blk * FPAD] = t + 2;   // done reading buf for step t+1
        }
        cur ^= 1;
    }
}

// ------------------------------------------------------------------
// Launcher
// ------------------------------------------------------------------
extern "C" void kernel_launch(void* const* d_in, const int* in_sizes, int n_in,
                              void* d_out, int out_size) {
    const float* x   = (const float*)d_in[0];   // [B, T, I]
    const float* W   = (const float*)d_in[1];   // [H, I]
    const float* U   = (const float*)d_in[2];   // [H, H]
    const float* b   = (const float*)d_in[3];   // [H]
    const float* tau = (const float*)d_in[4];   // [H]

    float* hfinal = (float*)d_out;              // [B, H]
    float* states = hfinal + B_SZ * H_SZ;       // [B, T, H]

    cudaFuncSetAttribute(recur_kernel,
                         cudaFuncAttributeMaxDynamicSharedMemorySize,
                         RECUR_SMEM);

    reset_kernel<<<32, 1024>>>();

    dim3 ggrid(H_SZ / GBN, (B_SZ * T_SZ) / GBM);
    gemm_xw<<<ggrid, 256>>>(x, W, states);

    recur_kernel<<<RBLK, 512, RECUR_SMEM>>>(states, hfinal, U, b, tau);
}

// round 13
// speedup vs baseline: 1.0502x; 1.0502x over previous
#include <cuda_runtime.h>
#include <math.h>

#define B_SZ 32
#define T_SZ 1024
#define I_SZ 512
#define H_SZ 1024
#define DT_C 0.1f

typedef unsigned long long ull;

// ---------------- f32x2 packed-math helpers (Blackwell FFMA2) -------------
__device__ __forceinline__ ull ffma2(ull a, ull b, ull c) {
    ull d; asm("fma.rn.f32x2 %0, %1, %2, %3;" : "=l"(d) : "l"(a), "l"(b), "l"(c)); return d;
}
__device__ __forceinline__ ull fadd2(ull a, ull b) {
    ull d; asm("add.rn.f32x2 %0, %1, %2;" : "=l"(d) : "l"(a), "l"(b)); return d;
}
__device__ __forceinline__ ull pack2(float lo, float hi) {
    ull d; asm("mov.b64 %0, {%1, %2};" : "=l"(d) : "f"(lo), "f"(hi)); return d;
}
__device__ __forceinline__ float2 unpack2(ull v) {
    float2 r; asm("mov.b64 {%0, %1}, %2;" : "=f"(r.x), "=f"(r.y) : "l"(v)); return r;
}
// Acquire load for producer-flag polls (orders subsequent loads after flag).
__device__ __forceinline__ int ld_acq(const volatile int* p) {
    int v;
    asm volatile("ld.acquire.gpu.global.s32 %0, [%1];"
                 : "=r"(v) : "l"((const int*)p) : "memory");
    return v;
}

// ------------------------------------------------------------------
// Persistent-kernel global state
// g_hT: TRIPLE-buffered transposed hidden state: [3][H][B]  (k-major).
// Depth-3 means the write at step t (buf (t+1)%3) only conflicts with
// reads at step t-2; the staging poll (g_arrive[peer] >= t) already
// implies peers finished staging steps t-1 and t-2 -> no write-
// permission flags needed at all.
// g_arrive[blk]: h for step t+1 published (set end of step t).
// ------------------------------------------------------------------
#define RBLK 128
#define FPAD 32                      // ints per flag slot (128B line)
__device__ float g_hT[3][H_SZ * B_SZ];
__device__ volatile int g_arrive[RBLK * FPAD];

__global__ void reset_kernel() {
    int idx = blockIdx.x * blockDim.x + threadIdx.x;
    if (idx < H_SZ * B_SZ) g_hT[0][idx] = 0.0f;
    if (idx < RBLK * FPAD) g_arrive[idx] = 0;
}

// ------------------------------------------------------------------
// xW GEMM: C[M=B*T, H] = X[M, I] @ W[H, I]^T   (fp32, FFMA2 inner)
// 128x64 block tile, BK=16, 256 threads  (R8/R11-proven)
// ------------------------------------------------------------------
#define GBM 128
#define GBN 64
#define GBK 16

union F4U { float4 f4; ull u[2]; };

__global__ void __launch_bounds__(256) gemm_xw(
    const float* __restrict__ X, const float* __restrict__ W,
    float* __restrict__ C)
{
    __shared__ float Xs[GBK][GBM];
    __shared__ float Ws[GBK][GBN + 4];
    const int tid = threadIdx.x;
    const int tx = tid & 15;   // 16 -> N
    const int ty = tid >> 4;   // 16 -> M
    const int m0 = blockIdx.y * GBM;
    const int n0 = blockIdx.x * GBN;

    ull acc2[4][4];   // [m-pair p][n j]
#pragma unroll
    for (int p = 0; p < 4; p++)
#pragma unroll
        for (int j = 0; j < 4; j++) acc2[p][j] = 0ull;

    for (int k0 = 0; k0 < I_SZ; k0 += GBK) {
#pragma unroll
        for (int pp = 0; pp < 2; pp++) {
            int q = tid + pp * 256;
            int row = q >> 2, qc = q & 3;
            float4 v = *(const float4*)(X + (size_t)(m0 + row) * I_SZ + k0 + qc * 4);
            Xs[qc * 4 + 0][row] = v.x; Xs[qc * 4 + 1][row] = v.y;
            Xs[qc * 4 + 2][row] = v.z; Xs[qc * 4 + 3][row] = v.w;
        }
        {
            int row = tid >> 2, qc = tid & 3;
            float4 v = *(const float4*)(W + (size_t)(n0 + row) * I_SZ + k0 + qc * 4);
            Ws[qc * 4 + 0][row] = v.x; Ws[qc * 4 + 1][row] = v.y;
            Ws[qc * 4 + 2][row] = v.z; Ws[qc * 4 + 3][row] = v.w;
        }
        __syncthreads();
#pragma unroll
        for (int kk = 0; kk < GBK; kk++) {
            F4U a0, a1;
            a0.f4 = *(const float4*)&Xs[kk][ty * 8];
            a1.f4 = *(const float4*)&Xs[kk][ty * 8 + 4];
            float4 bv = *(const float4*)&Ws[kk][tx * 4];
            ull bd[4];
            bd[0] = pack2(bv.x, bv.x); bd[1] = pack2(bv.y, bv.y);
            bd[2] = pack2(bv.z, bv.z); bd[3] = pack2(bv.w, bv.w);
            ull a2[4] = {a0.u[0], a0.u[1], a1.u[0], a1.u[1]};
#pragma unroll
            for (int p = 0; p < 4; p++)
#pragma unroll
                for (int j = 0; j < 4; j++)
                    acc2[p][j] = ffma2(a2[p], bd[j], acc2[p][j]);
        }
        __syncthreads();
    }
#pragma unroll
    for (int p = 0; p < 4; p++) {
        float2 c0 = unpack2(acc2[p][0]);
        float2 c1 = unpack2(acc2[p][1]);
        float2 c2 = unpack2(acc2[p][2]);
        float2 c3 = unpack2(acc2[p][3]);
        float4 lo = make_float4(c0.x, c1.x, c2.x, c3.x);
        float4 hi = make_float4(c0.y, c1.y, c2.y, c3.y);
        *(float4*)(C + (size_t)(m0 + ty * 8 + 2 * p)     * H_SZ + n0 + tx * 4) = lo;
        *(float4*)(C + (size_t)(m0 + ty * 8 + 2 * p + 1) * H_SZ + n0 + tx * 4) = hi;
    }
}

// ------------------------------------------------------------------
// Persistent recurrence kernel (R11 compute path; triple-buffer sync).
// grid = 128 blocks (64 j-tiles x 2 b-halves), 512 threads.
// Per step: [stage | sync | compute | STS | sync |
//            w0-3: reduce+epilogue+flag  (w4-15 fall through to next
//            iteration's staging, overlapping the epilogue)]
// ------------------------------------------------------------------
#define JT 16
#define BHALF 16
#define USTR 1025
#define HSTR 20
#define NPO 128
#define RECUR_SMEM ((JT * USTR + H_SZ * HSTR) * 4 + NPO * 64 * 8)

__device__ __forceinline__ void stage_chunk(float* hs, int gbase, int bg0,
                                            int ch, int lc, int t_tgt,
                                            int buf) {
    const volatile int* pf = &g_arrive[(gbase | ch) * FPAD];
    while (ld_acq(pf) < t_tgt) { }
    const float* gsrc = g_hT[buf] + bg0 + (size_t)(16 * ch) * B_SZ;
    float* hdst = hs + (16 * ch) * HSTR;
#pragma unroll
    for (int i = 0; i < 8; i++) {
        int f = lc + 8 * i;                 // 0..63 float4s in chunk
        int row = f >> 2, part = (f & 3) * 4;
        float4 v = __ldcg((const float4*)(gsrc + (size_t)row * B_SZ + part));
        float* d = hdst + row * HSTR + part;
        d[0] = v.x; d[1] = v.y; d[2] = v.z; d[3] = v.w;
    }
}

__global__ void __launch_bounds__(512, 1) recur_kernel(
    float* __restrict__ states,      // [B, T, H] (holds xW on entry, states on exit)
    float* __restrict__ hfinal,      // [B, H]
    const float* __restrict__ U,     // [H, H]
    const float* __restrict__ bias,  // [H]
    const float* __restrict__ tau)   // [H]
{
    extern __shared__ float sm[];
    float* Us = sm;                                 // [JT][USTR]
    float* hs = Us + JT * USTR;                     // [1024][HSTR]
    ull* red = (ull*)(hs + H_SZ * HSTR);            // [NPO][64]

    const int tid = threadIdx.x;
    const int blk = blockIdx.x;
    const int jt = blk & 63;
    const int bh = blk >> 6;
    const int j0 = jt * JT;
    const int bg0 = bh * BHALF;
    const int gbase = bh << 6;        // first block of this flag group

    const int tb = tid & 1;
    const int tj = (tid >> 1) & 3;
    const int ks = tid >> 3;      // 0..63

    // ---- staging chunk assignment (R12-proven split) ----
    // warps 0-3  (tid < 128): chunks jt..jt+15 (incl. self; staged after
    //   the epilogue -- self flag is set by then)
    // warps 4-15 (tid >=128): chunks jt+16..jt+63 (staged during the
    //   epilogue of warps 0-3)
    const int ch = (tid < 128) ? ((jt + (tid >> 3)) & 63)
                               : ((jt + 16 + ((tid - 128) >> 3)) & 63);
    const int lc = tid & 7;

    // ---- load U slab into smem: Us[row][k], row = 0..15 ----
    for (int q = tid; q < JT * (H_SZ / 4); q += 512) {
        int row = q >> 8;
        int c = (q & 255) * 4;
        float4 v = *(const float4*)(U + (size_t)(j0 + row) * H_SZ + c);
        float* d = Us + row * USTR + c;
        d[0] = v.x; d[1] = v.y; d[2] = v.z; d[3] = v.w;
    }

    // ---- epilogue (reader) setup: tid < 128, sr = tid & 15 ----
    int po = 0, sr = 0, jg = 0, bp = 0;
    float decay = 0.0f, biasj = 0.0f;
    size_t sidx0 = 0, sidx1 = 0;
    float xwA = 0.0f, xwB = 0.0f;
    if (tid < NPO) {
        int r = tid;
        po = ((r >> 1) & 1) | ((r & 1) << 1) | (((r >> 4) & 1) << 2)
           | (((r >> 5) & 1) << 3) | (((r >> 6) & 1) << 4)
           | (((r >> 2) & 1) << 5) | (((r >> 3) & 1) << 6);
        sr = r & 15;
        int j_loc = po >> 3;
        bp = po & 7;
        jg = j0 + j_loc;
        float it = 1.0f / tau[jg];
        decay = 1.0f - DT_C * it;
        biasj = bias[jg];
        int b_glob = bg0 + 2 * bp;
        sidx0 = (size_t)b_glob * T_SZ * H_SZ + jg;
        sidx1 = sidx0 + (size_t)T_SZ * H_SZ;
        xwA = __ldcg(states + sidx0);   // prefetch t = 0
        xwB = __ldcg(states + sidx1);
    }

    int cur = 0;    // buffer index = t % 3
    __syncthreads();

    for (int t = 0; t < T_SZ; t++) {
        // ---- stage h for step t from g_hT[cur]; per-chunk producer poll --
        stage_chunk(hs, gbase, bg0, ch, lc, t, cur);
        __syncthreads();

        // ---- compute: acc2[jj][m] over k = ks + 64*kq ----
        ull acc2[4][4];
#pragma unroll
        for (int jj = 0; jj < 4; jj++)
#pragma unroll
            for (int m = 0; m < 4; m++) acc2[jj][m] = 0ull;

        const float* urow = Us + tj * 4 * USTR + ks;
#pragma unroll
        for (int kq = 0; kq < 16; kq++) {
            int k = ks + 64 * kq;
            const float* hrow = hs + k * HSTR + 2 * tb;
            ull h0 = *(const ull*)(hrow + 0);
            ull h1 = *(const ull*)(hrow + 4);
            ull h2 = *(const ull*)(hrow + 8);
            ull h3 = *(const ull*)(hrow + 12);
#pragma unroll
            for (int jj = 0; jj < 4; jj++) {
                float us = urow[jj * USTR + 64 * kq];
                ull ud = pack2(us, us);
                acc2[jj][0] = ffma2(ud, h0, acc2[jj][0]);
                acc2[jj][1] = ffma2(ud, h1, acc2[jj][1]);
                acc2[jj][2] = ffma2(ud, h2, acc2[jj][2]);
                acc2[jj][3] = ffma2(ud, h3, acc2[jj][3]);
            }
        }

        // ---- write partials, XOR-swizzled (2-phase-optimal STS.64) ----
#pragma unroll
        for (int jj = 0; jj < 4; jj++)
#pragma unroll
            for (int m = 0; m < 4; m++) {
                int p = (tj * 4 + jj) * 8 + 2 * m + tb;
                int col = ks ^ ((m & 1) | (tb << 1) | (tj << 2));
                red[p * 64 + col] = acc2[jj][m];
            }
        __syncthreads();
        // After this sync, warps 4-15 are DONE with step t: they fall
        // through to the next iteration's staging (overlapping the
        // epilogue below). hs chunks they overwrite are gated on their
        // producers' t+1 flags; warps 0-3 below read only red + the own
        // chunk (jt), whose flag is set only after this epilogue.

        int nxt = cur + 1; if (nxt == 3) nxt = 0;
        if (tid < NPO) {
            // ---- reduce ----
            ull s01 = 0ull, s23 = 0ull;
#pragma unroll
            for (int i = 0; i < 64; i += 2) {
                s01 = fadd2(s01, red[po * 64 + (i ^ sr)]);
                s23 = fadd2(s23, red[po * 64 + ((i + 1) ^ sr)]);
            }
            float2 sum = unpack2(fadd2(s01, s23));
            float2 hold = *(const float2*)(hs + jg * HSTR + 2 * bp);
            // ---- pointwise epilogue + h publish ----
            float a0 = tanhf(xwA + sum.x + biasj);
            float a1 = tanhf(xwB + sum.y + biasj);
            float h0n = decay * hold.x + DT_C * a0;
            float h1n = decay * hold.y + DT_C * a1;
            size_t off = (size_t)t * H_SZ;
            __stcg(states + sidx0 + off, h0n);
            __stcg(states + sidx1 + off, h1n);
            float2 hn = make_float2(h0n, h1n);
            __stcg((float2*)(g_hT[nxt] + (size_t)jg * B_SZ + bg0 + 2 * bp), hn);
            if (t == T_SZ - 1) {
                __stcg(hfinal + (size_t)(bg0 + 2 * bp) * H_SZ + jg, h0n);
                __stcg(hfinal + (size_t)(bg0 + 2 * bp + 1) * H_SZ + jg, h1n);
            } else {
                xwA = __ldcg(states + sidx0 + off + H_SZ);   // prefetch t+1
                xwB = __ldcg(states + sidx1 + off + H_SZ);
            }
            // order the 128 epilogue threads' stores before the flag
            asm volatile("bar.sync 1, 128;" ::: "memory");
            if (tid == 0) {
                __threadfence();
                g_arrive[blk * FPAD] = t + 1;
            }
        }
        cur = nxt;
    }
}

// ------------------------------------------------------------------
// Launcher
// ------------------------------------------------------------------
extern "C" void kernel_launch(void* const* d_in, const int* in_sizes, int n_in,
                              void* d_out, int out_size) {
    const float* x   = (const float*)d_in[0];   // [B, T, I]
    const float* W   = (const float*)d_in[1];   // [H, I]
    const float* U   = (const float*)d_in[2];   // [H, H]
    const float* b   = (const float*)d_in[3];   // [H]
    const float* tau = (const float*)d_in[4];   // [H]

    float* hfinal = (float*)d_out;              // [B, H]
    float* states = hfinal + B_SZ * H_SZ;       // [B, T, H]

    cudaFuncSetAttribute(recur_kernel,
                         cudaFuncAttributeMaxDynamicSharedMemorySize,
                         RECUR_SMEM);

    reset_kernel<<<32, 1024>>>();

    dim3 ggrid(H_SZ / GBN, (B_SZ * T_SZ) / GBM);
    gemm_xw<<<ggrid, 256>>>(x, W, states);

    recur_kernel<<<RBLK, 512, RECUR_SMEM>>>(states, hfinal, U, b, tau);
}